// round 15
// baseline (speedup 1.0000x reference)
#include <cuda_runtime.h>
#include <cuda_fp16.h>
#include <cstdint>
#include <math.h>

#define B_  4
#define T_  4096
#define C_  2048
#define HS_ 128
#define MT  16384   // B_*T_

// Scratch (device globals per harness rules)
__device__ __align__(16) __half g_Qf[MT * HS_];   // pre-scaled by SCALE*log2(e)
__device__ __align__(16) __half g_Kf[MT * HS_];
__device__ __align__(16) __half g_Vf[MT * HS_];
__device__ __align__(16) __half g_Wt[3][HS_ * C_];
__device__ __align__(16) float  g_Op[2][MT][HS_]; // split-K partial O
__device__ float g_mP[2][MT];                     // split-K partial max (log2 dom)
__device__ float g_lP[2][MT];                     // split-K partial sum

// ---------------------------------------------------------------------------
// Helpers
// ---------------------------------------------------------------------------
__device__ __forceinline__ uint32_t smem_u32(const void* p) {
    uint32_t a;
    asm("{ .reg .u64 t; cvta.to.shared.u64 t, %1; cvt.u32.u64 %0, t; }" : "=r"(a) : "l"(p));
    return a;
}
__device__ __forceinline__ void cp_async16(uint32_t dst, const void* src) {
    asm volatile("cp.async.ca.shared.global [%0], [%1], 16;" :: "r"(dst), "l"(src));
}
__device__ __forceinline__ void ldm_x4(uint32_t* r, uint32_t addr) {
    asm volatile("ldmatrix.sync.aligned.m8n8.x4.shared.b16 {%0,%1,%2,%3}, [%4];"
        : "=r"(r[0]), "=r"(r[1]), "=r"(r[2]), "=r"(r[3]) : "r"(addr));
}
__device__ __forceinline__ void ldm_x4_t(uint32_t* r, uint32_t addr) {
    asm volatile("ldmatrix.sync.aligned.m8n8.x4.trans.shared.b16 {%0,%1,%2,%3}, [%4];"
        : "=r"(r[0]), "=r"(r[1]), "=r"(r[2]), "=r"(r[3]) : "r"(addr));
}
__device__ __forceinline__ void mma_f16(float* d, const uint32_t* a, uint32_t b0, uint32_t b1) {
    asm volatile("mma.sync.aligned.m16n8k16.row.col.f32.f16.f16.f32 "
        "{%0,%1,%2,%3}, {%4,%5,%6,%7}, {%8,%9}, {%0,%1,%2,%3};"
        : "+f"(d[0]), "+f"(d[1]), "+f"(d[2]), "+f"(d[3])
        : "r"(a[0]), "r"(a[1]), "r"(a[2]), "r"(a[3]), "r"(b0), "r"(b1));
}
__device__ __forceinline__ uint32_t pack_h2(float a, float b) {
    __half2 t = __floats2half2_rn(a, b);
    return *reinterpret_cast<uint32_t*>(&t);
}
__device__ __forceinline__ float ex2f(float x) {
    float y;
    asm("ex2.approx.f32 %0, %1;" : "=f"(y) : "f"(x));
    return y;
}

// ---------------------------------------------------------------------------
// Prep: W [2048,128] fp32 -> W^T fp16 [128,2048]
// ---------------------------------------------------------------------------
__global__ __launch_bounds__(256) void prep_w(
    const float* __restrict__ Wq, const float* __restrict__ Wk, const float* __restrict__ Wv)
{
    __shared__ float t[32][33];
    const int mi = blockIdx.z;
    const float* W = (mi == 0) ? Wq : ((mi == 1) ? Wk : Wv);
    const int k0 = blockIdx.x * 32, n0 = blockIdx.y * 32;
    const int tx = threadIdx.x & 31, ty = threadIdx.x >> 5;
#pragma unroll
    for (int i = 0; i < 32; i += 8)
        t[ty + i][tx] = W[(size_t)(k0 + ty + i) * HS_ + n0 + tx];
    __syncthreads();
#pragma unroll
    for (int i = 0; i < 32; i += 8) {
        float v = t[tx][ty + i];
        g_Wt[mi][(size_t)(n0 + ty + i) * C_ + (k0 + tx)] = __float2half(v);
    }
}

// ---------------------------------------------------------------------------
// QKV projection (fp16 mma, occ 2). Q output pre-scaled by SCALE*log2(e).
// ---------------------------------------------------------------------------
#define KC     64
#define NCHUNK (C_ / KC)
#define ASTRB  144
#define TILEB  (128 * ASTRB)
#define STAGEB (2 * TILEB)
#define SMEM_QKV (2 * STAGEB)

__global__ __launch_bounds__(256, 2) void qkv_mma(const float* __restrict__ x)
{
    extern __shared__ char smem[];
    const uint32_t sb = smem_u32(smem);
    const int tid  = threadIdx.x;
    const int lane = tid & 31, wid = tid >> 5;
    const int wm = wid >> 1, wn = wid & 1;
    const int mi = blockIdx.x;
    const int m0 = blockIdx.y * 128;

    const __half* Wt = g_Wt[mi];
    __half* out = (mi == 0) ? g_Qf : ((mi == 1) ? g_Kf : g_Vf);
    const float osc = (mi == 0) ? (0.08838834764831845f * 1.4426950408889634f) : 1.0f;

    float acc[2][8][4];
#pragma unroll
    for (int i = 0; i < 2; i++)
#pragma unroll
        for (int j = 0; j < 8; j++)
#pragma unroll
            for (int k = 0; k < 4; k++) acc[i][j][k] = 0.0f;

    auto loadB = [&](int s, int c) {
        const uint32_t bq = sb + s * STAGEB + TILEB;
#pragma unroll
        for (int t = 0; t < 4; t++) {
            const int idx = tid + t * 256;
            const int n = idx >> 3, kk = idx & 7;
            const char* src = (const char*)(Wt + (size_t)n * C_ + c * KC) + kk * 16;
            cp_async16(bq + (uint32_t)(n * ASTRB + kk * 16), src);
        }
        asm volatile("cp.async.commit_group;");
    };
    auto loadA = [&](uint2* ar, int c) {
#pragma unroll
        for (int t = 0; t < 8; t++) {
            const int idx = tid + t * 256;
            const int r = idx >> 4, f = idx & 15;
            float4 v = *(const float4*)(x + (size_t)(m0 + r) * C_ + c * KC + f * 4);
            ar[t].x = pack_h2(v.x, v.y);
            ar[t].y = pack_h2(v.z, v.w);
        }
    };
    auto storeA = [&](int s, const uint2* ar) {
        char* ad = smem + s * STAGEB;
#pragma unroll
        for (int t = 0; t < 8; t++) {
            const int idx = tid + t * 256;
            const int r = idx >> 4, f = idx & 15;
            *(uint2*)(ad + (uint32_t)(r * ASTRB + f * 8)) = ar[t];
        }
    };

    const uint32_t aRowOff = (uint32_t)((wm * 32 + (lane & 15)) * ASTRB + (lane >> 4) * 16);
    const uint32_t bRowOff = (uint32_t)((wn * 64 + (lane & 15)) * ASTRB + (lane >> 4) * 16);

    uint2 areg[8];
    loadB(0, 0);
    loadA(areg, 0);
    storeA(0, areg);
    asm volatile("cp.async.wait_group 0;" ::: "memory");
    __syncthreads();

    for (int c = 0; c < NCHUNK; c++) {
        const int s = c & 1;
        if (c + 1 < NCHUNK) {
            loadB(s ^ 1, c + 1);
            loadA(areg, c + 1);
        }
        const uint32_t ah = sb + s * STAGEB;
        const uint32_t bq = ah + TILEB;

#pragma unroll
        for (int ks = 0; ks < 4; ks++) {
            uint32_t aF[2][4], bF[4][4];
#pragma unroll
            for (int mt = 0; mt < 2; mt++)
                ldm_x4(aF[mt], ah + aRowOff + (uint32_t)(mt * 16 * ASTRB + ks * 32));
#pragma unroll
            for (int nt = 0; nt < 4; nt++)
                ldm_x4(bF[nt], bq + bRowOff + (uint32_t)(nt * 16 * ASTRB + ks * 32));
#pragma unroll
            for (int mt = 0; mt < 2; mt++) {
#pragma unroll
                for (int nt = 0; nt < 4; nt++) {
                    mma_f16(acc[mt][nt * 2],     aF[mt], bF[nt][0], bF[nt][2]);
                    mma_f16(acc[mt][nt * 2 + 1], aF[mt], bF[nt][1], bF[nt][3]);
                }
            }
        }

        if (c + 1 < NCHUNK) {
            storeA(s ^ 1, areg);
            asm volatile("cp.async.wait_group 0;" ::: "memory");
        }
        __syncthreads();
    }

    const int g = lane >> 2, tg = lane & 3;
#pragma unroll
    for (int mt = 0; mt < 2; mt++) {
#pragma unroll
        for (int nf = 0; nf < 8; nf++) {
            const int n0 = wn * 64 + (nf >> 1) * 16 + (nf & 1) * 8 + tg * 2;
            const int r0 = m0 + wm * 32 + mt * 16 + g;
            float* d = acc[mt][nf];
            *(uint32_t*)(out + (size_t)r0 * HS_ + n0)       = pack_h2(d[0] * osc, d[1] * osc);
            *(uint32_t*)(out + (size_t)(r0 + 8) * HS_ + n0) = pack_h2(d[2] * osc, d[3] * osc);
        }
    }
}

// ---------------------------------------------------------------------------
// Flash attention: BQ=128, BK=64, OCCUPANCY 2 (the one change vs R14).
// warp = 16 full q-rows, pairs {p,31-p}, split-K halves (each exactly qt+1
// 64-tiles), double-buffered K/V, 1 barrier per k-tile, exp2 softmax.
// smem 102 KB -> two CTAs per SM hide softmax/barrier bubbles.
// ---------------------------------------------------------------------------
#define FRSTR  272
#define QT_B   (128 * FRSTR)        // 34816
#define KT_B   (64 * FRSTR)         // 17408
#define OFF_Q  0
#define OFF_K0 QT_B
#define OFF_K1 (QT_B + KT_B)
#define OFF_V0 (QT_B + 2 * KT_B)
#define OFF_V1 (QT_B + 3 * KT_B)
#define SMEM_FL (QT_B + 4 * KT_B)   // 104448

__global__ __launch_bounds__(256, 2) void flash_mma()
{
    extern __shared__ char fsm[];
    const uint32_t sb = smem_u32(fsm);

    const int tid = threadIdx.x, lane = tid & 31, wid = tid >> 5;
    const int p = blockIdx.x, kh = blockIdx.y, b = blockIdx.z;

    const int g = lane >> 2, tg = lane & 3;
    const uint32_t laneA = (uint32_t)((lane & 15) * FRSTR + (lane >> 4) * 16);
    const int rloc0 = wid * 16 + g;               // local rows rloc0, rloc0+8

    auto load128 = [&](uint32_t dst, const __half* src) {
#pragma unroll
        for (int t = 0; t < 8; t++) {
            const int idx = tid + t * 256;
            const int r = idx >> 4, c = idx & 15;
            cp_async16(dst + (uint32_t)(r * FRSTR + c * 16), (const char*)src + r * 256 + c * 16);
        }
    };
    auto load64 = [&](uint32_t dst, const __half* src) {
#pragma unroll
        for (int t = 0; t < 4; t++) {
            const int idx = tid + t * 256;
            const int r = idx >> 4, c = idx & 15;
            cp_async16(dst + (uint32_t)(r * FRSTR + c * 16), (const char*)src + r * 256 + c * 16);
        }
    };

    for (int mem = 0; mem < 2; mem++) {
        const int qt = mem ? (31 - p) : p;
        const int qbase = qt * 128;
        const int nkt = 2 * (qt + 1);             // 64-wide k-tiles
        const int khalf = qt + 1;
        const int kt0 = kh ? khalf : 0;
        const int kt1 = kh ? nkt : khalf;         // always kt1 > kt0

        float oacc[16][4];
#pragma unroll
        for (int i = 0; i < 16; i++)
#pragma unroll
            for (int j = 0; j < 4; j++) oacc[i][j] = 0.0f;
        float m0_ = -1e30f, m1_ = -1e30f, l0_ = 0.0f, l1_ = 0.0f;

        load128(sb + OFF_Q, g_Qf + ((size_t)b * T_ + qbase) * HS_);
        load64(sb + OFF_K0, g_Kf + ((size_t)b * T_ + kt0 * 64) * HS_);
        load64(sb + OFF_V0, g_Vf + ((size_t)b * T_ + kt0 * 64) * HS_);
        asm volatile("cp.async.commit_group;");

        for (int kt = kt0; kt < kt1; kt++) {
            const int s = (kt - kt0) & 1;
            const uint32_t Kb = sb + (s ? OFF_K1 : OFF_K0);
            const uint32_t Vb = sb + (s ? OFF_V1 : OFF_V0);

            asm volatile("cp.async.wait_group 0;" ::: "memory");
            __syncthreads();                     // the ONE barrier per tile

            if (kt + 1 < kt1) {                  // prefetch into other buffer
                load64(sb + (s ? OFF_K0 : OFF_K1),
                       g_Kf + ((size_t)b * T_ + (kt + 1) * 64) * HS_);
                load64(sb + (s ? OFF_V0 : OFF_V1),
                       g_Vf + ((size_t)b * T_ + (kt + 1) * 64) * HS_);
                asm volatile("cp.async.commit_group;");
            }

            // ---- S = Q K^T (warp: 16m x 64n), exp2-domain scores ----
            float sacc[8][4];
#pragma unroll
            for (int i = 0; i < 8; i++)
#pragma unroll
                for (int j = 0; j < 4; j++) sacc[i][j] = 0.0f;

#pragma unroll
            for (int kf = 0; kf < 8; kf++) {
                uint32_t aF[4];
                ldm_x4(aF, sb + OFF_Q + (uint32_t)(wid * 16 * FRSTR) + laneA + kf * 32);
#pragma unroll
                for (int nt = 0; nt < 4; nt++) {
                    uint32_t kF[4];
                    ldm_x4(kF, Kb + (uint32_t)(nt * 16 * FRSTR) + laneA + kf * 32);
                    mma_f16(sacc[nt * 2],     aF, kF[0], kF[2]);
                    mma_f16(sacc[nt * 2 + 1], aF, kF[1], kF[3]);
                }
            }

            // ---- warp-local softmax ----
            if (kt >= nkt - 2) {                 // tiles containing the diagonal
#pragma unroll
                for (int nf = 0; nf < 8; nf++) {
                    const int c0 = kt * 64 + nf * 8 + tg * 2 - qbase;  // col rel. q
#pragma unroll
                    for (int j = 0; j < 2; j++) {
                        if (c0 + j > rloc0)     sacc[nf][j]     = -1e30f;
                        if (c0 + j > rloc0 + 8) sacc[nf][2 + j] = -1e30f;
                    }
                }
            }
            float mx0 = -1e30f, mx1 = -1e30f;
#pragma unroll
            for (int nf = 0; nf < 8; nf++) {
                mx0 = fmaxf(mx0, fmaxf(sacc[nf][0], sacc[nf][1]));
                mx1 = fmaxf(mx1, fmaxf(sacc[nf][2], sacc[nf][3]));
            }
            mx0 = fmaxf(mx0, __shfl_xor_sync(0xffffffffu, mx0, 1));
            mx0 = fmaxf(mx0, __shfl_xor_sync(0xffffffffu, mx0, 2));
            mx1 = fmaxf(mx1, __shfl_xor_sync(0xffffffffu, mx1, 1));
            mx1 = fmaxf(mx1, __shfl_xor_sync(0xffffffffu, mx1, 2));

            const float mn0 = fmaxf(m0_, mx0), mn1 = fmaxf(m1_, mx1);
            const float fac0 = ex2f(m0_ - mn0), fac1 = ex2f(m1_ - mn1);
            m0_ = mn0; m1_ = mn1;

            float rs0 = 0.0f, rs1 = 0.0f;
#pragma unroll
            for (int nf = 0; nf < 8; nf++) {
                float p0 = ex2f(sacc[nf][0] - mn0);
                float p1 = ex2f(sacc[nf][1] - mn0);
                float p2 = ex2f(sacc[nf][2] - mn1);
                float p3 = ex2f(sacc[nf][3] - mn1);
                sacc[nf][0] = p0; sacc[nf][1] = p1; sacc[nf][2] = p2; sacc[nf][3] = p3;
                rs0 += p0 + p1; rs1 += p2 + p3;
            }
            rs0 += __shfl_xor_sync(0xffffffffu, rs0, 1);
            rs0 += __shfl_xor_sync(0xffffffffu, rs0, 2);
            rs1 += __shfl_xor_sync(0xffffffffu, rs1, 1);
            rs1 += __shfl_xor_sync(0xffffffffu, rs1, 2);
            l0_ = l0_ * fac0 + rs0;
            l1_ = l1_ * fac1 + rs1;
#pragma unroll
            for (int dt = 0; dt < 16; dt++) {
                oacc[dt][0] *= fac0; oacc[dt][1] *= fac0;
                oacc[dt][2] *= fac1; oacc[dt][3] *= fac1;
            }

            // ---- O += P V (register P, warp 16m x 128d, 64 k-rows) ----
#pragma unroll
            for (int ks = 0; ks < 4; ks++) {
                float* s0 = sacc[ks * 2];
                float* s1 = sacc[ks * 2 + 1];
                uint32_t pa[4];
                pa[0] = pack_h2(s0[0], s0[1]);
                pa[1] = pack_h2(s0[2], s0[3]);
                pa[2] = pack_h2(s1[0], s1[1]);
                pa[3] = pack_h2(s1[2], s1[3]);
#pragma unroll
                for (int dt = 0; dt < 8; dt++) {
                    uint32_t vF[4];
                    ldm_x4_t(vF, Vb + (uint32_t)(ks * 16 * FRSTR) + laneA + dt * 32);
                    mma_f16(oacc[dt * 2],     pa, vF[0], vF[1]);
                    mma_f16(oacc[dt * 2 + 1], pa, vF[2], vF[3]);
                }
            }
        }

        // ---- write split-K partials ----
        {
            const size_t row0 = (size_t)b * T_ + qbase + rloc0;
            const size_t row1 = row0 + 8;
#pragma unroll
            for (int dt = 0; dt < 16; dt++) {
                const int c = dt * 8 + tg * 2;
                *(float2*)&g_Op[kh][row0][c] = make_float2(oacc[dt][0], oacc[dt][1]);
                *(float2*)&g_Op[kh][row1][c] = make_float2(oacc[dt][2], oacc[dt][3]);
            }
            if (tg == 0) {
                g_mP[kh][row0] = m0_; g_lP[kh][row0] = l0_;
                g_mP[kh][row1] = m1_; g_lP[kh][row1] = l1_;
            }
        }
        __syncthreads();   // smem reuse for the pair's second member
    }
}

// ---------------------------------------------------------------------------
// Combine the two split-K halves: 8 floats/thread (R14 version).
// ---------------------------------------------------------------------------
__global__ __launch_bounds__(256) void combine_k(float* __restrict__ y)
{
    const int idx = blockIdx.x * 256 + threadIdx.x;   // one thread = 8 floats
    const int row = idx >> 4;
    const int c = (idx & 15) * 8;
    const float m0 = g_mP[0][row], m1 = g_mP[1][row];
    const float l0 = g_lP[0][row], l1 = g_lP[1][row];
    float4 a0 = *(const float4*)&g_Op[0][row][c];
    float4 a1 = *(const float4*)&g_Op[0][row][c + 4];
    float4 b0 = *(const float4*)&g_Op[1][row][c];
    float4 b1 = *(const float4*)&g_Op[1][row][c + 4];
    const float mf = fmaxf(m0, m1);
    const float w0 = ex2f(m0 - mf), w1 = ex2f(m1 - mf);
    const float inv = 1.0f / (w0 * l0 + w1 * l1);
    const float s0 = w0 * inv, s1 = w1 * inv;
    float4 r0, r1;
    r0.x = s0 * a0.x + s1 * b0.x;
    r0.y = s0 * a0.y + s1 * b0.y;
    r0.z = s0 * a0.z + s1 * b0.z;
    r0.w = s0 * a0.w + s1 * b0.w;
    r1.x = s0 * a1.x + s1 * b1.x;
    r1.y = s0 * a1.y + s1 * b1.y;
    r1.z = s0 * a1.z + s1 * b1.z;
    r1.w = s0 * a1.w + s1 * b1.w;
    float* yo = y + (size_t)row * HS_ + c;
    *(float4*)yo       = r0;
    *(float4*)(yo + 4) = r1;
}

// ---------------------------------------------------------------------------
extern "C" void kernel_launch(void* const* d_in, const int* in_sizes, int n_in,
                              void* d_out, int out_size)
{
    const float* x  = (const float*)d_in[0];
    const float* Wq = (const float*)d_in[1];
    const float* Wk = (const float*)d_in[2];
    const float* Wv = (const float*)d_in[3];
    float* y = (float*)d_out;
    (void)in_sizes; (void)n_in; (void)out_size;

    prep_w<<<dim3(64, 4, 3), 256>>>(Wq, Wk, Wv);

    cudaFuncSetAttribute(qkv_mma, cudaFuncAttributeMaxDynamicSharedMemorySize, SMEM_QKV);
    qkv_mma<<<dim3(3, 128), 256, SMEM_QKV>>>(x);

    cudaFuncSetAttribute(flash_mma, cudaFuncAttributeMaxDynamicSharedMemorySize, SMEM_FL);
    flash_mma<<<dim3(16, 2, 4), 256, SMEM_FL>>>();

    combine_k<<<(MT * 16) / 256, 256>>>(y);
}

// round 16
// speedup vs baseline: 1.1000x; 1.1000x over previous
#include <cuda_runtime.h>
#include <cuda_fp16.h>
#include <cstdint>
#include <math.h>

#define B_  4
#define T_  4096
#define C_  2048
#define HS_ 128
#define MT  16384   // B_*T_

// Scratch (device globals per harness rules)
__device__ __align__(16) __half g_Qf[MT * HS_];   // pre-scaled by SCALE*log2(e)
__device__ __align__(16) __half g_Kf[MT * HS_];
__device__ __align__(16) __half g_Vf[MT * HS_];
__device__ __align__(16) __half g_Wt[3][HS_ * C_];
__device__ __align__(16) float  g_Op[2][MT][HS_]; // split-K partial O
__device__ float g_mP[2][MT];                     // split-K partial max (log2 dom)
__device__ float g_lP[2][MT];                     // split-K partial sum

// ---------------------------------------------------------------------------
// Helpers
// ---------------------------------------------------------------------------
__device__ __forceinline__ uint32_t smem_u32(const void* p) {
    uint32_t a;
    asm("{ .reg .u64 t; cvta.to.shared.u64 t, %1; cvt.u32.u64 %0, t; }" : "=r"(a) : "l"(p));
    return a;
}
__device__ __forceinline__ void cp_async16(uint32_t dst, const void* src) {
    asm volatile("cp.async.ca.shared.global [%0], [%1], 16;" :: "r"(dst), "l"(src));
}
__device__ __forceinline__ void ldm_x4(uint32_t* r, uint32_t addr) {
    asm volatile("ldmatrix.sync.aligned.m8n8.x4.shared.b16 {%0,%1,%2,%3}, [%4];"
        : "=r"(r[0]), "=r"(r[1]), "=r"(r[2]), "=r"(r[3]) : "r"(addr));
}
__device__ __forceinline__ void ldm_x4_t(uint32_t* r, uint32_t addr) {
    asm volatile("ldmatrix.sync.aligned.m8n8.x4.trans.shared.b16 {%0,%1,%2,%3}, [%4];"
        : "=r"(r[0]), "=r"(r[1]), "=r"(r[2]), "=r"(r[3]) : "r"(addr));
}
__device__ __forceinline__ void mma_f16(float* d, const uint32_t* a, uint32_t b0, uint32_t b1) {
    asm volatile("mma.sync.aligned.m16n8k16.row.col.f32.f16.f16.f32 "
        "{%0,%1,%2,%3}, {%4,%5,%6,%7}, {%8,%9}, {%0,%1,%2,%3};"
        : "+f"(d[0]), "+f"(d[1]), "+f"(d[2]), "+f"(d[3])
        : "r"(a[0]), "r"(a[1]), "r"(a[2]), "r"(a[3]), "r"(b0), "r"(b1));
}
__device__ __forceinline__ uint32_t pack_h2(float a, float b) {
    __half2 t = __floats2half2_rn(a, b);
    return *reinterpret_cast<uint32_t*>(&t);
}
__device__ __forceinline__ float ex2f(float x) {
    float y;
    asm("ex2.approx.f32 %0, %1;" : "=f"(y) : "f"(x));
    return y;
}

// ---------------------------------------------------------------------------
// Prep: W [2048,128] fp32 -> W^T fp16 [128,2048]
// ---------------------------------------------------------------------------
__global__ __launch_bounds__(256) void prep_w(
    const float* __restrict__ Wq, const float* __restrict__ Wk, const float* __restrict__ Wv)
{
    __shared__ float t[32][33];
    const int mi = blockIdx.z;
    const float* W = (mi == 0) ? Wq : ((mi == 1) ? Wk : Wv);
    const int k0 = blockIdx.x * 32, n0 = blockIdx.y * 32;
    const int tx = threadIdx.x & 31, ty = threadIdx.x >> 5;
#pragma unroll
    for (int i = 0; i < 32; i += 8)
        t[ty + i][tx] = W[(size_t)(k0 + ty + i) * HS_ + n0 + tx];
    __syncthreads();
#pragma unroll
    for (int i = 0; i < 32; i += 8) {
        float v = t[tx][ty + i];
        g_Wt[mi][(size_t)(n0 + ty + i) * C_ + (k0 + tx)] = __float2half(v);
    }
}

// ---------------------------------------------------------------------------
// QKV projection (fp16 mma, occ 2). Q output pre-scaled by SCALE*log2(e).
// ---------------------------------------------------------------------------
#define KC     64
#define NCHUNK (C_ / KC)
#define ASTRB  144
#define TILEB  (128 * ASTRB)
#define STAGEB (2 * TILEB)
#define SMEM_QKV (2 * STAGEB)

__global__ __launch_bounds__(256, 2) void qkv_mma(const float* __restrict__ x)
{
    extern __shared__ char smem[];
    const uint32_t sb = smem_u32(smem);
    const int tid  = threadIdx.x;
    const int lane = tid & 31, wid = tid >> 5;
    const int wm = wid >> 1, wn = wid & 1;
    const int mi = blockIdx.x;
    const int m0 = blockIdx.y * 128;

    const __half* Wt = g_Wt[mi];
    __half* out = (mi == 0) ? g_Qf : ((mi == 1) ? g_Kf : g_Vf);
    const float osc = (mi == 0) ? (0.08838834764831845f * 1.4426950408889634f) : 1.0f;

    float acc[2][8][4];
#pragma unroll
    for (int i = 0; i < 2; i++)
#pragma unroll
        for (int j = 0; j < 8; j++)
#pragma unroll
            for (int k = 0; k < 4; k++) acc[i][j][k] = 0.0f;

    auto loadB = [&](int s, int c) {
        const uint32_t bq = sb + s * STAGEB + TILEB;
#pragma unroll
        for (int t = 0; t < 4; t++) {
            const int idx = tid + t * 256;
            const int n = idx >> 3, kk = idx & 7;
            const char* src = (const char*)(Wt + (size_t)n * C_ + c * KC) + kk * 16;
            cp_async16(bq + (uint32_t)(n * ASTRB + kk * 16), src);
        }
        asm volatile("cp.async.commit_group;");
    };
    auto loadA = [&](uint2* ar, int c) {
#pragma unroll
        for (int t = 0; t < 8; t++) {
            const int idx = tid + t * 256;
            const int r = idx >> 4, f = idx & 15;
            float4 v = *(const float4*)(x + (size_t)(m0 + r) * C_ + c * KC + f * 4);
            ar[t].x = pack_h2(v.x, v.y);
            ar[t].y = pack_h2(v.z, v.w);
        }
    };
    auto storeA = [&](int s, const uint2* ar) {
        char* ad = smem + s * STAGEB;
#pragma unroll
        for (int t = 0; t < 8; t++) {
            const int idx = tid + t * 256;
            const int r = idx >> 4, f = idx & 15;
            *(uint2*)(ad + (uint32_t)(r * ASTRB + f * 8)) = ar[t];
        }
    };

    const uint32_t aRowOff = (uint32_t)((wm * 32 + (lane & 15)) * ASTRB + (lane >> 4) * 16);
    const uint32_t bRowOff = (uint32_t)((wn * 64 + (lane & 15)) * ASTRB + (lane >> 4) * 16);

    uint2 areg[8];
    loadB(0, 0);
    loadA(areg, 0);
    storeA(0, areg);
    asm volatile("cp.async.wait_group 0;" ::: "memory");
    __syncthreads();

    for (int c = 0; c < NCHUNK; c++) {
        const int s = c & 1;
        if (c + 1 < NCHUNK) {
            loadB(s ^ 1, c + 1);
            loadA(areg, c + 1);
        }
        const uint32_t ah = sb + s * STAGEB;
        const uint32_t bq = ah + TILEB;

#pragma unroll
        for (int ks = 0; ks < 4; ks++) {
            uint32_t aF[2][4], bF[4][4];
#pragma unroll
            for (int mt = 0; mt < 2; mt++)
                ldm_x4(aF[mt], ah + aRowOff + (uint32_t)(mt * 16 * ASTRB + ks * 32));
#pragma unroll
            for (int nt = 0; nt < 4; nt++)
                ldm_x4(bF[nt], bq + bRowOff + (uint32_t)(nt * 16 * ASTRB + ks * 32));
#pragma unroll
            for (int mt = 0; mt < 2; mt++) {
#pragma unroll
                for (int nt = 0; nt < 4; nt++) {
                    mma_f16(acc[mt][nt * 2],     aF[mt], bF[nt][0], bF[nt][2]);
                    mma_f16(acc[mt][nt * 2 + 1], aF[mt], bF[nt][1], bF[nt][3]);
                }
            }
        }

        if (c + 1 < NCHUNK) {
            storeA(s ^ 1, areg);
            asm volatile("cp.async.wait_group 0;" ::: "memory");
        }
        __syncthreads();
    }

    const int g = lane >> 2, tg = lane & 3;
#pragma unroll
    for (int mt = 0; mt < 2; mt++) {
#pragma unroll
        for (int nf = 0; nf < 8; nf++) {
            const int n0 = wn * 64 + (nf >> 1) * 16 + (nf & 1) * 8 + tg * 2;
            const int r0 = m0 + wm * 32 + mt * 16 + g;
            float* d = acc[mt][nf];
            *(uint32_t*)(out + (size_t)r0 * HS_ + n0)       = pack_h2(d[0] * osc, d[1] * osc);
            *(uint32_t*)(out + (size_t)(r0 + 8) * HS_ + n0) = pack_h2(d[2] * osc, d[3] * osc);
        }
    }
}

// ---------------------------------------------------------------------------
// Flash attention (R14 champion + Q-fragment hoist): BQ=BK=128, warp = 16
// full q-rows, pairs {p,31-p}, split-K halves, double-buffered K/V, 1 barrier
// per k-tile, exp2 softmax, fp32 partial O. Q A-fragments are loaded into
// registers once per member (Q is k-loop invariant) instead of per tile.
// ---------------------------------------------------------------------------
#define FRSTR  272
#define FT     (128 * FRSTR)        // 34816
#define OFF_Q  0
#define OFF_K0 FT
#define OFF_K1 (2 * FT)
#define OFF_V0 (3 * FT)
#define OFF_V1 (4 * FT)
#define SMEM_FL (5 * FT)            // 174080

__global__ __launch_bounds__(256, 1) void flash_mma()
{
    extern __shared__ char fsm[];
    const uint32_t sb = smem_u32(fsm);

    const int tid = threadIdx.x, lane = tid & 31, wid = tid >> 5;
    const int p = blockIdx.x, kh = blockIdx.y, b = blockIdx.z;

    const int g = lane >> 2, tg = lane & 3;
    const uint32_t laneA = (uint32_t)((lane & 15) * FRSTR + (lane >> 4) * 16);
    const int rloc0 = wid * 16 + g;               // local rows rloc0, rloc0+8

    auto load128 = [&](uint32_t dst, const __half* src) {
#pragma unroll
        for (int t = 0; t < 8; t++) {
            const int idx = tid + t * 256;
            const int r = idx >> 4, c = idx & 15;
            cp_async16(dst + (uint32_t)(r * FRSTR + c * 16), (const char*)src + r * 256 + c * 16);
        }
    };

    for (int mem = 0; mem < 2; mem++) {
        const int qt = mem ? (31 - p) : p;
        const int qbase = qt * 128;
        const int nkt = qt + 1;
        const int khalf = (nkt + 1) >> 1;
        const int kt0 = kh ? khalf : 0;
        const int kt1 = kh ? nkt : khalf;

        float oacc[16][4];
#pragma unroll
        for (int i = 0; i < 16; i++)
#pragma unroll
            for (int j = 0; j < 4; j++) oacc[i][j] = 0.0f;
        float m0_ = -1e30f, m1_ = -1e30f, l0_ = 0.0f, l1_ = 0.0f;

        uint32_t qF[8][4];   // hoisted Q fragments (k-loop invariant)

        if (kt0 < kt1) {
            load128(sb + OFF_Q, g_Qf + ((size_t)b * T_ + qbase) * HS_);
            load128(sb + OFF_K0, g_Kf + ((size_t)b * T_ + kt0 * 128) * HS_);
            load128(sb + OFF_V0, g_Vf + ((size_t)b * T_ + kt0 * 128) * HS_);
            asm volatile("cp.async.commit_group;");

            for (int kt = kt0; kt < kt1; kt++) {
                const int s = (kt - kt0) & 1;
                const uint32_t Kb = sb + (s ? OFF_K1 : OFF_K0);
                const uint32_t Vb = sb + (s ? OFF_V1 : OFF_V0);

                asm volatile("cp.async.wait_group 0;" ::: "memory");
                __syncthreads();                     // the ONE barrier per tile

                if (kt + 1 < kt1) {                  // prefetch into other buffer
                    load128(sb + (s ? OFF_K0 : OFF_K1),
                            g_Kf + ((size_t)b * T_ + (kt + 1) * 128) * HS_);
                    load128(sb + (s ? OFF_V0 : OFF_V1),
                            g_Vf + ((size_t)b * T_ + (kt + 1) * 128) * HS_);
                    asm volatile("cp.async.commit_group;");
                }

                if (kt == kt0) {                     // hoist Q fragments once
#pragma unroll
                    for (int kf = 0; kf < 8; kf++)
                        ldm_x4(qF[kf], sb + OFF_Q + (uint32_t)(wid * 16 * FRSTR) + laneA + kf * 32);
                }

                // ---- S = Q K^T (warp: 16m x 128n), exp2-domain scores ----
                float sacc[16][4];
#pragma unroll
                for (int i = 0; i < 16; i++)
#pragma unroll
                    for (int j = 0; j < 4; j++) sacc[i][j] = 0.0f;

#pragma unroll
                for (int kf = 0; kf < 8; kf++) {
#pragma unroll
                    for (int nt = 0; nt < 8; nt++) {
                        uint32_t kF[4];
                        ldm_x4(kF, Kb + (uint32_t)(nt * 16 * FRSTR) + laneA + kf * 32);
                        mma_f16(sacc[nt * 2],     qF[kf], kF[0], kF[2]);
                        mma_f16(sacc[nt * 2 + 1], qF[kf], kF[1], kF[3]);
                    }
                }

                // ---- warp-local softmax ----
                if (kt == qt) {                      // mask only on diagonal tile
#pragma unroll
                    for (int nf = 0; nf < 16; nf++) {
                        const int c0 = nf * 8 + tg * 2;
#pragma unroll
                        for (int j = 0; j < 2; j++) {
                            if (c0 + j > rloc0)     sacc[nf][j]     = -1e30f;
                            if (c0 + j > rloc0 + 8) sacc[nf][2 + j] = -1e30f;
                        }
                    }
                }
                float mx0 = -1e30f, mx1 = -1e30f;
#pragma unroll
                for (int nf = 0; nf < 16; nf++) {
                    mx0 = fmaxf(mx0, fmaxf(sacc[nf][0], sacc[nf][1]));
                    mx1 = fmaxf(mx1, fmaxf(sacc[nf][2], sacc[nf][3]));
                }
                mx0 = fmaxf(mx0, __shfl_xor_sync(0xffffffffu, mx0, 1));
                mx0 = fmaxf(mx0, __shfl_xor_sync(0xffffffffu, mx0, 2));
                mx1 = fmaxf(mx1, __shfl_xor_sync(0xffffffffu, mx1, 1));
                mx1 = fmaxf(mx1, __shfl_xor_sync(0xffffffffu, mx1, 2));

                const float mn0 = fmaxf(m0_, mx0), mn1 = fmaxf(m1_, mx1);
                const float fac0 = ex2f(m0_ - mn0), fac1 = ex2f(m1_ - mn1);
                m0_ = mn0; m1_ = mn1;

                float rs0 = 0.0f, rs1 = 0.0f;
#pragma unroll
                for (int nf = 0; nf < 16; nf++) {
                    float p0 = ex2f(sacc[nf][0] - mn0);
                    float p1 = ex2f(sacc[nf][1] - mn0);
                    float p2 = ex2f(sacc[nf][2] - mn1);
                    float p3 = ex2f(sacc[nf][3] - mn1);
                    sacc[nf][0] = p0; sacc[nf][1] = p1; sacc[nf][2] = p2; sacc[nf][3] = p3;
                    rs0 += p0 + p1; rs1 += p2 + p3;
                }
                rs0 += __shfl_xor_sync(0xffffffffu, rs0, 1);
                rs0 += __shfl_xor_sync(0xffffffffu, rs0, 2);
                rs1 += __shfl_xor_sync(0xffffffffu, rs1, 1);
                rs1 += __shfl_xor_sync(0xffffffffu, rs1, 2);
                l0_ = l0_ * fac0 + rs0;
                l1_ = l1_ * fac1 + rs1;
#pragma unroll
                for (int dt = 0; dt < 16; dt++) {
                    oacc[dt][0] *= fac0; oacc[dt][1] *= fac0;
                    oacc[dt][2] *= fac1; oacc[dt][3] *= fac1;
                }

                // ---- O += P V (register P, warp 16m x 128d) ----
#pragma unroll
                for (int ks = 0; ks < 8; ks++) {
                    float* s0 = sacc[ks * 2];
                    float* s1 = sacc[ks * 2 + 1];
                    uint32_t pa[4];
                    pa[0] = pack_h2(s0[0], s0[1]);
                    pa[1] = pack_h2(s0[2], s0[3]);
                    pa[2] = pack_h2(s1[0], s1[1]);
                    pa[3] = pack_h2(s1[2], s1[3]);
#pragma unroll
                    for (int dt = 0; dt < 8; dt++) {
                        uint32_t vF[4];
                        ldm_x4_t(vF, Vb + (uint32_t)(ks * 16 * FRSTR) + laneA + dt * 32);
                        mma_f16(oacc[dt * 2],     pa, vF[0], vF[1]);
                        mma_f16(oacc[dt * 2 + 1], pa, vF[2], vF[3]);
                    }
                }
            }
        }

        // ---- write split-K partials ----
        {
            const size_t row0 = (size_t)b * T_ + qbase + rloc0;
            const size_t row1 = row0 + 8;
#pragma unroll
            for (int dt = 0; dt < 16; dt++) {
                const int c = dt * 8 + tg * 2;
                *(float2*)&g_Op[kh][row0][c] = make_float2(oacc[dt][0], oacc[dt][1]);
                *(float2*)&g_Op[kh][row1][c] = make_float2(oacc[dt][2], oacc[dt][3]);
            }
            if (tg == 0) {
                g_mP[kh][row0] = m0_; g_lP[kh][row0] = l0_;
                g_mP[kh][row1] = m1_; g_lP[kh][row1] = l1_;
            }
        }
        __syncthreads();   // smem reuse for the pair's second member
    }
}

// ---------------------------------------------------------------------------
// Combine the two split-K halves: 8 floats/thread (R14 version).
// ---------------------------------------------------------------------------
__global__ __launch_bounds__(256) void combine_k(float* __restrict__ y)
{
    const int idx = blockIdx.x * 256 + threadIdx.x;   // one thread = 8 floats
    const int row = idx >> 4;
    const int c = (idx & 15) * 8;
    const float m0 = g_mP[0][row], m1 = g_mP[1][row];
    const float l0 = g_lP[0][row], l1 = g_lP[1][row];
    float4 a0 = *(const float4*)&g_Op[0][row][c];
    float4 a1 = *(const float4*)&g_Op[0][row][c + 4];
    float4 b0 = *(const float4*)&g_Op[1][row][c];
    float4 b1 = *(const float4*)&g_Op[1][row][c + 4];
    const float mf = fmaxf(m0, m1);
    const float w0 = ex2f(m0 - mf), w1 = ex2f(m1 - mf);
    const float inv = 1.0f / (w0 * l0 + w1 * l1);
    const float s0 = w0 * inv, s1 = w1 * inv;
    float4 r0, r1;
    r0.x = s0 * a0.x + s1 * b0.x;
    r0.y = s0 * a0.y + s1 * b0.y;
    r0.z = s0 * a0.z + s1 * b0.z;
    r0.w = s0 * a0.w + s1 * b0.w;
    r1.x = s0 * a1.x + s1 * b1.x;
    r1.y = s0 * a1.y + s1 * b1.y;
    r1.z = s0 * a1.z + s1 * b1.z;
    r1.w = s0 * a1.w + s1 * b1.w;
    float* yo = y + (size_t)row * HS_ + c;
    *(float4*)yo       = r0;
    *(float4*)(yo + 4) = r1;
}

// ---------------------------------------------------------------------------
extern "C" void kernel_launch(void* const* d_in, const int* in_sizes, int n_in,
                              void* d_out, int out_size)
{
    const float* x  = (const float*)d_in[0];
    const float* Wq = (const float*)d_in[1];
    const float* Wk = (const float*)d_in[2];
    const float* Wv = (const float*)d_in[3];
    float* y = (float*)d_out;
    (void)in_sizes; (void)n_in; (void)out_size;

    prep_w<<<dim3(64, 4, 3), 256>>>(Wq, Wk, Wv);

    cudaFuncSetAttribute(qkv_mma, cudaFuncAttributeMaxDynamicSharedMemorySize, SMEM_QKV);
    qkv_mma<<<dim3(3, 128), 256, SMEM_QKV>>>(x);

    cudaFuncSetAttribute(flash_mma, cudaFuncAttributeMaxDynamicSharedMemorySize, SMEM_FL);
    flash_mma<<<dim3(16, 2, 4), 256, SMEM_FL>>>();

    combine_k<<<(MT * 16) / 256, 256>>>(y);
}

// round 17
// speedup vs baseline: 1.1069x; 1.0063x over previous
#include <cuda_runtime.h>
#include <cuda_fp16.h>
#include <cstdint>
#include <math.h>

#define B_  4
#define T_  4096
#define C_  2048
#define HS_ 128
#define MT  16384   // B_*T_

// Scratch (device globals per harness rules)
__device__ __align__(16) __half g_Qf[MT * HS_];   // pre-scaled by SCALE*log2(e)
__device__ __align__(16) __half g_Kf[MT * HS_];
__device__ __align__(16) __half g_Vf[MT * HS_];
__device__ __align__(16) __half g_Wt[3][HS_ * C_];
__device__ __align__(16) float  g_Op[2][MT][HS_]; // split-K partial O
__device__ float g_mP[2][MT];                     // split-K partial max (log2 dom)
__device__ float g_lP[2][MT];                     // split-K partial sum

// ---------------------------------------------------------------------------
// Helpers
// ---------------------------------------------------------------------------
__device__ __forceinline__ uint32_t smem_u32(const void* p) {
    uint32_t a;
    asm("{ .reg .u64 t; cvta.to.shared.u64 t, %1; cvt.u32.u64 %0, t; }" : "=r"(a) : "l"(p));
    return a;
}
__device__ __forceinline__ void cp_async16(uint32_t dst, const void* src) {
    asm volatile("cp.async.ca.shared.global [%0], [%1], 16;" :: "r"(dst), "l"(src));
}
__device__ __forceinline__ void ldm_x4(uint32_t* r, uint32_t addr) {
    asm volatile("ldmatrix.sync.aligned.m8n8.x4.shared.b16 {%0,%1,%2,%3}, [%4];"
        : "=r"(r[0]), "=r"(r[1]), "=r"(r[2]), "=r"(r[3]) : "r"(addr));
}
__device__ __forceinline__ void ldm_x4_t(uint32_t* r, uint32_t addr) {
    asm volatile("ldmatrix.sync.aligned.m8n8.x4.trans.shared.b16 {%0,%1,%2,%3}, [%4];"
        : "=r"(r[0]), "=r"(r[1]), "=r"(r[2]), "=r"(r[3]) : "r"(addr));
}
__device__ __forceinline__ void mma_f16(float* d, const uint32_t* a, uint32_t b0, uint32_t b1) {
    asm volatile("mma.sync.aligned.m16n8k16.row.col.f32.f16.f16.f32 "
        "{%0,%1,%2,%3}, {%4,%5,%6,%7}, {%8,%9}, {%0,%1,%2,%3};"
        : "+f"(d[0]), "+f"(d[1]), "+f"(d[2]), "+f"(d[3])
        : "r"(a[0]), "r"(a[1]), "r"(a[2]), "r"(a[3]), "r"(b0), "r"(b1));
}
__device__ __forceinline__ uint32_t pack_h2(float a, float b) {
    __half2 t = __floats2half2_rn(a, b);
    return *reinterpret_cast<uint32_t*>(&t);
}
__device__ __forceinline__ float ex2f(float x) {
    float y;
    asm("ex2.approx.f32 %0, %1;" : "=f"(y) : "f"(x));
    return y;
}

// ---------------------------------------------------------------------------
// Prep: W [2048,128] fp32 -> W^T fp16 [128,2048]
// ---------------------------------------------------------------------------
__global__ __launch_bounds__(256) void prep_w(
    const float* __restrict__ Wq, const float* __restrict__ Wk, const float* __restrict__ Wv)
{
    __shared__ float t[32][33];
    const int mi = blockIdx.z;
    const float* W = (mi == 0) ? Wq : ((mi == 1) ? Wk : Wv);
    const int k0 = blockIdx.x * 32, n0 = blockIdx.y * 32;
    const int tx = threadIdx.x & 31, ty = threadIdx.x >> 5;
#pragma unroll
    for (int i = 0; i < 32; i += 8)
        t[ty + i][tx] = W[(size_t)(k0 + ty + i) * HS_ + n0 + tx];
    __syncthreads();
#pragma unroll
    for (int i = 0; i < 32; i += 8) {
        float v = t[tx][ty + i];
        g_Wt[mi][(size_t)(n0 + ty + i) * C_ + (k0 + tx)] = __float2half(v);
    }
}

// ---------------------------------------------------------------------------
// QKV projection (fp16 mma, occ 2). Q output pre-scaled by SCALE*log2(e).
// ---------------------------------------------------------------------------
#define KC     64
#define NCHUNK (C_ / KC)
#define ASTRB  144
#define TILEB  (128 * ASTRB)
#define STAGEB (2 * TILEB)
#define SMEM_QKV (2 * STAGEB)

__global__ __launch_bounds__(256, 2) void qkv_mma(const float* __restrict__ x)
{
    extern __shared__ char smem[];
    const uint32_t sb = smem_u32(smem);
    const int tid  = threadIdx.x;
    const int lane = tid & 31, wid = tid >> 5;
    const int wm = wid >> 1, wn = wid & 1;
    const int mi = blockIdx.x;
    const int m0 = blockIdx.y * 128;

    const __half* Wt = g_Wt[mi];
    __half* out = (mi == 0) ? g_Qf : ((mi == 1) ? g_Kf : g_Vf);
    const float osc = (mi == 0) ? (0.08838834764831845f * 1.4426950408889634f) : 1.0f;

    float acc[2][8][4];
#pragma unroll
    for (int i = 0; i < 2; i++)
#pragma unroll
        for (int j = 0; j < 8; j++)
#pragma unroll
            for (int k = 0; k < 4; k++) acc[i][j][k] = 0.0f;

    auto loadB = [&](int s, int c) {
        const uint32_t bq = sb + s * STAGEB + TILEB;
#pragma unroll
        for (int t = 0; t < 4; t++) {
            const int idx = tid + t * 256;
            const int n = idx >> 3, kk = idx & 7;
            const char* src = (const char*)(Wt + (size_t)n * C_ + c * KC) + kk * 16;
            cp_async16(bq + (uint32_t)(n * ASTRB + kk * 16), src);
        }
        asm volatile("cp.async.commit_group;");
    };
    auto loadA = [&](uint2* ar, int c) {
#pragma unroll
        for (int t = 0; t < 8; t++) {
            const int idx = tid + t * 256;
            const int r = idx >> 4, f = idx & 15;
            float4 v = *(const float4*)(x + (size_t)(m0 + r) * C_ + c * KC + f * 4);
            ar[t].x = pack_h2(v.x, v.y);
            ar[t].y = pack_h2(v.z, v.w);
        }
    };
    auto storeA = [&](int s, const uint2* ar) {
        char* ad = smem + s * STAGEB;
#pragma unroll
        for (int t = 0; t < 8; t++) {
            const int idx = tid + t * 256;
            const int r = idx >> 4, f = idx & 15;
            *(uint2*)(ad + (uint32_t)(r * ASTRB + f * 8)) = ar[t];
        }
    };

    const uint32_t aRowOff = (uint32_t)((wm * 32 + (lane & 15)) * ASTRB + (lane >> 4) * 16);
    const uint32_t bRowOff = (uint32_t)((wn * 64 + (lane & 15)) * ASTRB + (lane >> 4) * 16);

    uint2 areg[8];
    loadB(0, 0);
    loadA(areg, 0);
    storeA(0, areg);
    asm volatile("cp.async.wait_group 0;" ::: "memory");
    __syncthreads();

    for (int c = 0; c < NCHUNK; c++) {
        const int s = c & 1;
        if (c + 1 < NCHUNK) {
            loadB(s ^ 1, c + 1);
            loadA(areg, c + 1);
        }
        const uint32_t ah = sb + s * STAGEB;
        const uint32_t bq = ah + TILEB;

#pragma unroll
        for (int ks = 0; ks < 4; ks++) {
            uint32_t aF[2][4], bF[4][4];
#pragma unroll
            for (int mt = 0; mt < 2; mt++)
                ldm_x4(aF[mt], ah + aRowOff + (uint32_t)(mt * 16 * ASTRB + ks * 32));
#pragma unroll
            for (int nt = 0; nt < 4; nt++)
                ldm_x4(bF[nt], bq + bRowOff + (uint32_t)(nt * 16 * ASTRB + ks * 32));
#pragma unroll
            for (int mt = 0; mt < 2; mt++) {
#pragma unroll
                for (int nt = 0; nt < 4; nt++) {
                    mma_f16(acc[mt][nt * 2],     aF[mt], bF[nt][0], bF[nt][2]);
                    mma_f16(acc[mt][nt * 2 + 1], aF[mt], bF[nt][1], bF[nt][3]);
                }
            }
        }

        if (c + 1 < NCHUNK) {
            storeA(s ^ 1, areg);
            asm volatile("cp.async.wait_group 0;" ::: "memory");
        }
        __syncthreads();
    }

    const int g = lane >> 2, tg = lane & 3;
#pragma unroll
    for (int mt = 0; mt < 2; mt++) {
#pragma unroll
        for (int nf = 0; nf < 8; nf++) {
            const int n0 = wn * 64 + (nf >> 1) * 16 + (nf & 1) * 8 + tg * 2;
            const int r0 = m0 + wm * 32 + mt * 16 + g;
            float* d = acc[mt][nf];
            *(uint32_t*)(out + (size_t)r0 * HS_ + n0)       = pack_h2(d[0] * osc, d[1] * osc);
            *(uint32_t*)(out + (size_t)(r0 + 8) * HS_ + n0) = pack_h2(d[2] * osc, d[3] * osc);
        }
    }
}

// ---------------------------------------------------------------------------
// Flash attention (R16 champion + balanced schedule): BQ=BK=128, warp = 16
// full q-rows, split-K halves, double-buffered K/V, 1 barrier per k-tile,
// exp2 softmax, Q-fragment hoist, fp32 partial O.
// NEW schedule: grid (33,1,4). CTA c<31 processes members (qt=c,kh=0) and
// (qt=30-c,kh=1): ceil((c+1)/2)+floor((31-c)/2) = 16 tiles for every c.
// CTA c=31 -> (31,0) alone (16 tiles); c=32 -> (31,1) alone (16 tiles).
// Every CTA does exactly 16 k-tiles (vs 17/16 imbalance before).
// ---------------------------------------------------------------------------
#define FRSTR  272
#define FT     (128 * FRSTR)        // 34816
#define OFF_Q  0
#define OFF_K0 FT
#define OFF_K1 (2 * FT)
#define OFF_V0 (3 * FT)
#define OFF_V1 (4 * FT)
#define SMEM_FL (5 * FT)            // 174080

__global__ __launch_bounds__(256, 1) void flash_mma()
{
    extern __shared__ char fsm[];
    const uint32_t sb = smem_u32(fsm);

    const int tid = threadIdx.x, lane = tid & 31, wid = tid >> 5;
    const int cix = blockIdx.x, b = blockIdx.z;

    const int g = lane >> 2, tg = lane & 3;
    const uint32_t laneA = (uint32_t)((lane & 15) * FRSTR + (lane >> 4) * 16);
    const int rloc0 = wid * 16 + g;               // local rows rloc0, rloc0+8

    auto load128 = [&](uint32_t dst, const __half* src) {
#pragma unroll
        for (int t = 0; t < 8; t++) {
            const int idx = tid + t * 256;
            const int r = idx >> 4, c = idx & 15;
            cp_async16(dst + (uint32_t)(r * FRSTR + c * 16), (const char*)src + r * 256 + c * 16);
        }
    };

    const int nmem = (cix < 31) ? 2 : 1;

    for (int mem = 0; mem < nmem; mem++) {
        int qt, kh;
        if (cix < 31) { qt = mem ? (30 - cix) : cix; kh = mem; }
        else          { qt = 31;                     kh = cix - 31; }

        const int qbase = qt * 128;
        const int nkt = qt + 1;
        const int khalf = (nkt + 1) >> 1;
        const int kt0 = kh ? khalf : 0;
        const int kt1 = kh ? nkt : khalf;

        float oacc[16][4];
#pragma unroll
        for (int i = 0; i < 16; i++)
#pragma unroll
            for (int j = 0; j < 4; j++) oacc[i][j] = 0.0f;
        float m0_ = -1e30f, m1_ = -1e30f, l0_ = 0.0f, l1_ = 0.0f;

        uint32_t qF[8][4];   // hoisted Q fragments (k-loop invariant)

        if (kt0 < kt1) {
            load128(sb + OFF_Q, g_Qf + ((size_t)b * T_ + qbase) * HS_);
            load128(sb + OFF_K0, g_Kf + ((size_t)b * T_ + kt0 * 128) * HS_);
            load128(sb + OFF_V0, g_Vf + ((size_t)b * T_ + kt0 * 128) * HS_);
            asm volatile("cp.async.commit_group;");

            for (int kt = kt0; kt < kt1; kt++) {
                const int s = (kt - kt0) & 1;
                const uint32_t Kb = sb + (s ? OFF_K1 : OFF_K0);
                const uint32_t Vb = sb + (s ? OFF_V1 : OFF_V0);

                asm volatile("cp.async.wait_group 0;" ::: "memory");
                __syncthreads();                     // the ONE barrier per tile

                if (kt + 1 < kt1) {                  // prefetch into other buffer
                    load128(sb + (s ? OFF_K0 : OFF_K1),
                            g_Kf + ((size_t)b * T_ + (kt + 1) * 128) * HS_);
                    load128(sb + (s ? OFF_V0 : OFF_V1),
                            g_Vf + ((size_t)b * T_ + (kt + 1) * 128) * HS_);
                    asm volatile("cp.async.commit_group;");
                }

                if (kt == kt0) {                     // hoist Q fragments once
#pragma unroll
                    for (int kf = 0; kf < 8; kf++)
                        ldm_x4(qF[kf], sb + OFF_Q + (uint32_t)(wid * 16 * FRSTR) + laneA + kf * 32);
                }

                // ---- S = Q K^T (warp: 16m x 128n), exp2-domain scores ----
                float sacc[16][4];
#pragma unroll
                for (int i = 0; i < 16; i++)
#pragma unroll
                    for (int j = 0; j < 4; j++) sacc[i][j] = 0.0f;

#pragma unroll
                for (int kf = 0; kf < 8; kf++) {
#pragma unroll
                    for (int nt = 0; nt < 8; nt++) {
                        uint32_t kF[4];
                        ldm_x4(kF, Kb + (uint32_t)(nt * 16 * FRSTR) + laneA + kf * 32);
                        mma_f16(sacc[nt * 2],     qF[kf], kF[0], kF[2]);
                        mma_f16(sacc[nt * 2 + 1], qF[kf], kF[1], kF[3]);
                    }
                }

                // ---- warp-local softmax ----
                if (kt == qt) {                      // mask only on diagonal tile
#pragma unroll
                    for (int nf = 0; nf < 16; nf++) {
                        const int c0 = nf * 8 + tg * 2;
#pragma unroll
                        for (int j = 0; j < 2; j++) {
                            if (c0 + j > rloc0)     sacc[nf][j]     = -1e30f;
                            if (c0 + j > rloc0 + 8) sacc[nf][2 + j] = -1e30f;
                        }
                    }
                }
                float mx0 = -1e30f, mx1 = -1e30f;
#pragma unroll
                for (int nf = 0; nf < 16; nf++) {
                    mx0 = fmaxf(mx0, fmaxf(sacc[nf][0], sacc[nf][1]));
                    mx1 = fmaxf(mx1, fmaxf(sacc[nf][2], sacc[nf][3]));
                }
                mx0 = fmaxf(mx0, __shfl_xor_sync(0xffffffffu, mx0, 1));
                mx0 = fmaxf(mx0, __shfl_xor_sync(0xffffffffu, mx0, 2));
                mx1 = fmaxf(mx1, __shfl_xor_sync(0xffffffffu, mx1, 1));
                mx1 = fmaxf(mx1, __shfl_xor_sync(0xffffffffu, mx1, 2));

                const float mn0 = fmaxf(m0_, mx0), mn1 = fmaxf(m1_, mx1);
                const float fac0 = ex2f(m0_ - mn0), fac1 = ex2f(m1_ - mn1);
                m0_ = mn0; m1_ = mn1;

                float rs0 = 0.0f, rs1 = 0.0f;
#pragma unroll
                for (int nf = 0; nf < 16; nf++) {
                    float p0 = ex2f(sacc[nf][0] - mn0);
                    float p1 = ex2f(sacc[nf][1] - mn0);
                    float p2 = ex2f(sacc[nf][2] - mn1);
                    float p3 = ex2f(sacc[nf][3] - mn1);
                    sacc[nf][0] = p0; sacc[nf][1] = p1; sacc[nf][2] = p2; sacc[nf][3] = p3;
                    rs0 += p0 + p1; rs1 += p2 + p3;
                }
                rs0 += __shfl_xor_sync(0xffffffffu, rs0, 1);
                rs0 += __shfl_xor_sync(0xffffffffu, rs0, 2);
                rs1 += __shfl_xor_sync(0xffffffffu, rs1, 1);
                rs1 += __shfl_xor_sync(0xffffffffu, rs1, 2);
                l0_ = l0_ * fac0 + rs0;
                l1_ = l1_ * fac1 + rs1;
#pragma unroll
                for (int dt = 0; dt < 16; dt++) {
                    oacc[dt][0] *= fac0; oacc[dt][1] *= fac0;
                    oacc[dt][2] *= fac1; oacc[dt][3] *= fac1;
                }

                // ---- O += P V (register P, warp 16m x 128d) ----
#pragma unroll
                for (int ks = 0; ks < 8; ks++) {
                    float* s0 = sacc[ks * 2];
                    float* s1 = sacc[ks * 2 + 1];
                    uint32_t pa[4];
                    pa[0] = pack_h2(s0[0], s0[1]);
                    pa[1] = pack_h2(s0[2], s0[3]);
                    pa[2] = pack_h2(s1[0], s1[1]);
                    pa[3] = pack_h2(s1[2], s1[3]);
#pragma unroll
                    for (int dt = 0; dt < 8; dt++) {
                        uint32_t vF[4];
                        ldm_x4_t(vF, Vb + (uint32_t)(ks * 16 * FRSTR) + laneA + dt * 32);
                        mma_f16(oacc[dt * 2],     pa, vF[0], vF[1]);
                        mma_f16(oacc[dt * 2 + 1], pa, vF[2], vF[3]);
                    }
                }
            }
        }

        // ---- write split-K partials ----
        {
            const size_t row0 = (size_t)b * T_ + qbase + rloc0;
            const size_t row1 = row0 + 8;
#pragma unroll
            for (int dt = 0; dt < 16; dt++) {
                const int c = dt * 8 + tg * 2;
                *(float2*)&g_Op[kh][row0][c] = make_float2(oacc[dt][0], oacc[dt][1]);
                *(float2*)&g_Op[kh][row1][c] = make_float2(oacc[dt][2], oacc[dt][3]);
            }
            if (tg == 0) {
                g_mP[kh][row0] = m0_; g_lP[kh][row0] = l0_;
                g_mP[kh][row1] = m1_; g_lP[kh][row1] = l1_;
            }
        }
        __syncthreads();   // smem reuse for the second member
    }
}

// ---------------------------------------------------------------------------
// Combine the two split-K halves: 8 floats/thread (R14 version).
// ---------------------------------------------------------------------------
__global__ __launch_bounds__(256) void combine_k(float* __restrict__ y)
{
    const int idx = blockIdx.x * 256 + threadIdx.x;   // one thread = 8 floats
    const int row = idx >> 4;
    const int c = (idx & 15) * 8;
    const float m0 = g_mP[0][row], m1 = g_mP[1][row];
    const float l0 = g_lP[0][row], l1 = g_lP[1][row];
    float4 a0 = *(const float4*)&g_Op[0][row][c];
    float4 a1 = *(const float4*)&g_Op[0][row][c + 4];
    float4 b0 = *(const float4*)&g_Op[1][row][c];
    float4 b1 = *(const float4*)&g_Op[1][row][c + 4];
    const float mf = fmaxf(m0, m1);
    const float w0 = ex2f(m0 - mf), w1 = ex2f(m1 - mf);
    const float inv = 1.0f / (w0 * l0 + w1 * l1);
    const float s0 = w0 * inv, s1 = w1 * inv;
    float4 r0, r1;
    r0.x = s0 * a0.x + s1 * b0.x;
    r0.y = s0 * a0.y + s1 * b0.y;
    r0.z = s0 * a0.z + s1 * b0.z;
    r0.w = s0 * a0.w + s1 * b0.w;
    r1.x = s0 * a1.x + s1 * b1.x;
    r1.y = s0 * a1.y + s1 * b1.y;
    r1.z = s0 * a1.z + s1 * b1.z;
    r1.w = s0 * a1.w + s1 * b1.w;
    float* yo = y + (size_t)row * HS_ + c;
    *(float4*)yo       = r0;
    *(float4*)(yo + 4) = r1;
}

// ---------------------------------------------------------------------------
extern "C" void kernel_launch(void* const* d_in, const int* in_sizes, int n_in,
                              void* d_out, int out_size)
{
    const float* x  = (const float*)d_in[0];
    const float* Wq = (const float*)d_in[1];
    const float* Wk = (const float*)d_in[2];
    const float* Wv = (const float*)d_in[3];
    float* y = (float*)d_out;
    (void)in_sizes; (void)n_in; (void)out_size;

    prep_w<<<dim3(64, 4, 3), 256>>>(Wq, Wk, Wv);

    cudaFuncSetAttribute(qkv_mma, cudaFuncAttributeMaxDynamicSharedMemorySize, SMEM_QKV);
    qkv_mma<<<dim3(3, 128), 256, SMEM_QKV>>>(x);

    cudaFuncSetAttribute(flash_mma, cudaFuncAttributeMaxDynamicSharedMemorySize, SMEM_FL);
    flash_mma<<<dim3(33, 1, 4), 256, SMEM_FL>>>();

    combine_k<<<(MT * 16) / 256, 256>>>(y);
}